// round 15
// baseline (speedup 1.0000x reference)
#include <cuda_runtime.h>
#include <stdint.h>

#define DIM       300
#define VEC4      (DIM / 4)          // 75 float4 per row
#define VMAX      200000
#define KMAX      16
#define NBLOCKS   592                // 4 per SM (148 SMs)
#define NTHREADS  256
#define WPB       (NTHREADS / 32)    // 8 warps per block
#define NWARPS    (NBLOCKS * WPB)    // 4736
#define ROWS_PER_ITER 4
#define H_CARVE   20000              // rows pinned via evict_last (24 MB = default carveout)
#define H_NORMAL  100000             // rows [H_CARVE, H_NORMAL) evict_normal (96 MB of ~102 MB normal L2)

// Scratch (no cudaMalloc allowed; __device__ globals are the sanctioned path)
__device__ float    g_scores[VMAX];
__device__ unsigned g_done = 0;

__device__ __forceinline__ float dot4(float4 a, float4 b)
{
    return a.x * b.x + a.y * b.y + a.z * b.z + a.w * b.w;
}

// ld.global.nc.v4 with an L2 cache-eviction policy attached
__device__ __forceinline__ float4 ldg_pol(const float4* __restrict__ p, uint64_t pol)
{
    float4 v;
    asm volatile("ld.global.nc.L2::cache_hint.v4.f32 {%0,%1,%2,%3}, [%4], %5;"
                 : "=f"(v.x), "=f"(v.y), "=f"(v.z), "=f"(v.w)
                 : "l"(p), "l"(pol));
    return v;
}

// ---------------------------------------------------------------------------
// Fused kernel — three-class L2 residency (carveout is fixed at ~24 MB, so the
// bulk of the resident set lives in the NORMAL section instead):
//   rows [0, H_CARVE)         : evict_last   -> persisting carveout (24 MB)
//   rows [H_CARVE, H_NORMAL)  : evict_normal -> normal L2 section (~96 MB);
//                                streaming class below is evicted before these
//   rows [H_NORMAL, V)        : evict_first  -> stream, evict self first
//   Phase 2 (last block): top-K over g_scores, write out.
// ---------------------------------------------------------------------------
__global__ __launch_bounds__(NTHREADS) void fused_kernel(const int* __restrict__ wordid,
                                                         const float* __restrict__ emb,
                                                         const int* __restrict__ topk_p,
                                                         float* __restrict__ out,
                                                         int out_size,
                                                         int V,
                                                         int Hc,
                                                         int Hn)
{
    const int lane = threadIdx.x & 31;
    const int warp = blockIdx.x * WPB + (threadIdx.x >> 5);

    uint64_t pol_last, pol_norm, pol_first;
    asm("createpolicy.fractional.L2::evict_last.b64   %0, 1.0;" : "=l"(pol_last));
    asm("createpolicy.fractional.L2::evict_normal.b64 %0, 1.0;" : "=l"(pol_norm));
    asm("createpolicy.fractional.L2::evict_first.b64  %0, 1.0;" : "=l"(pol_first));

    const float4 zero = make_float4(0.f, 0.f, 0.f, 0.f);
    const bool   t2   = (lane + 64) < VEC4;     // lanes 0..10 do the 3rd load

    // ---- query vector in registers (carveout policy; hot every replay) ----
    const int w = __ldg(wordid);
    const float4* __restrict__ wp =
        reinterpret_cast<const float4*>(emb + (size_t)w * DIM);
    const float4 b0 = ldg_pol(wp + lane,      pol_last);
    const float4 b1 = ldg_pol(wp + lane + 32, pol_last);
    const float4 b2 = t2 ? ldg_pol(wp + lane + 64, pol_last) : zero;

    // ---- phase 1: 4 rows per iteration, all 12 loads issued before use ----
    for (int base = warp; base < V; base += ROWS_PER_ITER * NWARPS) {
        float4   a[ROWS_PER_ITER][3];
        int      rr[ROWS_PER_ITER];
        bool     hv[ROWS_PER_ITER];

        #pragma unroll
        for (int j = 0; j < ROWS_PER_ITER; j++) {
            rr[j] = base + j * NWARPS;
            hv[j] = rr[j] < V;
            const int safe = hv[j] ? rr[j] : 0;
            const uint64_t pol = (safe < Hc) ? pol_last
                               : (safe < Hn) ? pol_norm
                                             : pol_first;
            const float4* __restrict__ rp =
                reinterpret_cast<const float4*>(emb + (size_t)safe * DIM);
            a[j][0] = ldg_pol(rp + lane,      pol);
            a[j][1] = ldg_pol(rp + lane + 32, pol);
            a[j][2] = t2 ? ldg_pol(rp + lane + 64, pol) : zero;
        }

        #pragma unroll
        for (int j = 0; j < ROWS_PER_ITER; j++) {
            float s = dot4(a[j][0], b0) + dot4(a[j][1], b1) + dot4(a[j][2], b2);
            #pragma unroll
            for (int off = 16; off; off >>= 1)
                s += __shfl_xor_sync(0xFFFFFFFFu, s, off);
            if (lane == 0 && hv[j])
                g_scores[rr[j]] = s;
        }
    }

    // ---- last-block-done handoff ----
    __shared__ bool isLast;
    __threadfence();
    if (threadIdx.x == 0) {
        unsigned prev = atomicAdd(&g_done, 1u);
        isLast = (prev == (unsigned)(gridDim.x - 1));
    }
    __syncthreads();
    if (!isLast) return;
    __threadfence();   // acquire: all blocks' score stores visible

    // ---- phase 2: top-K over g_scores ----
    int K = *topk_p + 1;
    if (K > KMAX) K = KMAX;
    if (K < 1)    K = 1;

    __shared__ float svals[NTHREADS * KMAX];
    __shared__ int   sids [NTHREADS * KMAX];

    float lv[KMAX];
    int   li[KMAX];
    #pragma unroll
    for (int i = 0; i < KMAX; i++) { lv[i] = -3.0e38f; li[i] = 0x7FFFFFFF; }
    float kmin = -3.0e38f;

    const int t = threadIdx.x;
    for (int r = t; r < V; r += NTHREADS) {
        float v = g_scores[r];
        if (v > kmin) {
            int pos = K - 1;
            while (pos > 0 && lv[pos - 1] < v) {
                lv[pos] = lv[pos - 1];
                li[pos] = li[pos - 1];
                pos--;
            }
            lv[pos] = v;
            li[pos] = r;
            kmin = lv[K - 1];
        }
    }

    for (int i = 0; i < K; i++) {
        svals[t * KMAX + i] = lv[i];
        sids [t * KMAX + i] = li[i];
    }
    __syncthreads();

    if (t == 0) {
        float fv[KMAX];
        int   fi[KMAX];
        #pragma unroll
        for (int i = 0; i < KMAX; i++) { fv[i] = -3.0e38f; fi[i] = 0x7FFFFFFF; }
        float fmin = -3.0e38f;

        for (int tt = 0; tt < NTHREADS; tt++) {
            for (int kk = 0; kk < K; kk++) {
                float v  = svals[tt * KMAX + kk];
                int   id = sids [tt * KMAX + kk];
                if (id == 0x7FFFFFFF) break;
                bool better = (v > fmin) || (v == fmin && id < fi[K - 1]);
                if (better) {
                    int pos = K - 1;
                    while (pos > 0 &&
                           (fv[pos - 1] < v ||
                            (fv[pos - 1] == v && fi[pos - 1] > id))) {
                        fv[pos] = fv[pos - 1];
                        fi[pos] = fi[pos - 1];
                        pos--;
                    }
                    fv[pos] = v;
                    fi[pos] = id;
                    fmin = fv[K - 1];
                }
            }
        }

        for (int i = 0; i < K && i < out_size; i++)
            out[i] = fv[i];
        if (out_size >= 2 * K) {
            for (int i = 0; i < K; i++)
                out[K + i] = (float)fi[i];
        }

        g_done = 0;   // reset for next (deterministic) replay
    }
}

// ---------------------------------------------------------------------------
extern "C" void kernel_launch(void* const* d_in, const int* in_sizes, int n_in,
                              void* d_out, int out_size)
{
    const int*   wordid = (const int*)  d_in[0];
    const float* emb    = (const float*)d_in[1];
    const int*   topk   = (const int*)  d_in[2];
    float*       out    = (float*)      d_out;

    const int V = in_sizes[1] / DIM;   // 200000

    int Hc = H_CARVE;
    int Hn = H_NORMAL;
    if (Hc > V) Hc = V;
    if (Hn > V) Hn = V;

    fused_kernel<<<NBLOCKS, NTHREADS>>>(wordid, emb, topk, out, out_size,
                                        V, Hc, Hn);
}

// round 16
// speedup vs baseline: 2.1678x; 2.1678x over previous
#include <cuda_runtime.h>
#include <stdint.h>

#define DIM       300
#define VEC4      (DIM / 4)          // 75 float4 per row
#define VMAX      200000
#define KMAX      16
#define NBLOCKS   592                // 4 per SM (148 SMs)
#define NTHREADS  256
#define WPB       (NTHREADS / 32)    // 8 warps per block
#define NWARPS    (NBLOCKS * WPB)    // 4736
#define ROWS_PER_ITER 4
#define H_CARVE   20000              // 24 MB == default persisting carveout (exact fit)

// Scratch (no cudaMalloc allowed; __device__ globals are the sanctioned path)
__device__ float    g_scores[VMAX];
__device__ unsigned g_done = 0;

__device__ __forceinline__ float dot4(float4 a, float4 b)
{
    return a.x * b.x + a.y * b.y + a.z * b.z + a.w * b.w;
}

// ld.global.nc.v4 with an L2 cache-eviction policy attached
__device__ __forceinline__ float4 ldg_pol(const float4* __restrict__ p, uint64_t pol)
{
    float4 v;
    asm volatile("ld.global.nc.L2::cache_hint.v4.f32 {%0,%1,%2,%3}, [%4], %5;"
                 : "=f"(v.x), "=f"(v.y), "=f"(v.z), "=f"(v.w)
                 : "l"(p), "l"(pol));
    return v;
}

// ---------------------------------------------------------------------------
// Fused kernel:
//   rows [0, H_CARVE) : evict_last  -> exactly fills the 24 MB persisting
//                                      carveout; retained across graph replays
//   rows [H_CARVE, V) : evict_first -> stream over C2C each replay
//   Phase 2 (last block): vectorized per-thread top-K + parallel tree merge.
// ---------------------------------------------------------------------------
__global__ __launch_bounds__(NTHREADS) void fused_kernel(const int* __restrict__ wordid,
                                                         const float* __restrict__ emb,
                                                         const int* __restrict__ topk_p,
                                                         float* __restrict__ out,
                                                         int out_size,
                                                         int V,
                                                         int Hc)
{
    const int lane = threadIdx.x & 31;
    const int warp = blockIdx.x * WPB + (threadIdx.x >> 5);

    uint64_t pol_last, pol_first;
    asm("createpolicy.fractional.L2::evict_last.b64  %0, 1.0;" : "=l"(pol_last));
    asm("createpolicy.fractional.L2::evict_first.b64 %0, 1.0;" : "=l"(pol_first));

    const float4 zero = make_float4(0.f, 0.f, 0.f, 0.f);
    const bool   t2   = (lane + 64) < VEC4;     // lanes 0..10 do the 3rd load

    // ---- query vector in registers (carveout policy; hot every replay) ----
    const int w = __ldg(wordid);
    const float4* __restrict__ wp =
        reinterpret_cast<const float4*>(emb + (size_t)w * DIM);
    const float4 b0 = ldg_pol(wp + lane,      pol_last);
    const float4 b1 = ldg_pol(wp + lane + 32, pol_last);
    const float4 b2 = t2 ? ldg_pol(wp + lane + 64, pol_last) : zero;

    // ---- phase 1: 4 rows per iteration, all 12 loads issued before use ----
    for (int base = warp; base < V; base += ROWS_PER_ITER * NWARPS) {
        float4   a[ROWS_PER_ITER][3];
        int      rr[ROWS_PER_ITER];
        bool     hv[ROWS_PER_ITER];

        #pragma unroll
        for (int j = 0; j < ROWS_PER_ITER; j++) {
            rr[j] = base + j * NWARPS;
            hv[j] = rr[j] < V;
            const int safe = hv[j] ? rr[j] : 0;
            const uint64_t pol = (safe < Hc) ? pol_last : pol_first;
            const float4* __restrict__ rp =
                reinterpret_cast<const float4*>(emb + (size_t)safe * DIM);
            a[j][0] = ldg_pol(rp + lane,      pol);
            a[j][1] = ldg_pol(rp + lane + 32, pol);
            a[j][2] = t2 ? ldg_pol(rp + lane + 64, pol) : zero;
        }

        #pragma unroll
        for (int j = 0; j < ROWS_PER_ITER; j++) {
            float s = dot4(a[j][0], b0) + dot4(a[j][1], b1) + dot4(a[j][2], b2);
            #pragma unroll
            for (int off = 16; off; off >>= 1)
                s += __shfl_xor_sync(0xFFFFFFFFu, s, off);
            if (lane == 0 && hv[j])
                g_scores[rr[j]] = s;
        }
    }

    // ---- last-block-done handoff ----
    __shared__ bool isLast;
    __threadfence();
    if (threadIdx.x == 0) {
        unsigned prev = atomicAdd(&g_done, 1u);
        isLast = (prev == (unsigned)(gridDim.x - 1));
    }
    __syncthreads();
    if (!isLast) return;
    __threadfence();   // acquire: all blocks' score stores visible

    // ---- phase 2: top-K over g_scores ----
    int K = *topk_p + 1;
    if (K > KMAX) K = KMAX;
    if (K < 1)    K = 1;

    __shared__ float svals[NTHREADS * KMAX];
    __shared__ int   sids [NTHREADS * KMAX];

    float lv[KMAX];
    int   li[KMAX];
    #pragma unroll
    for (int i = 0; i < KMAX; i++) { lv[i] = -3.0e38f; li[i] = 0x7FFFFFFF; }
    float kmin = -3.0e38f;

    const int t = threadIdx.x;

    // vectorized scan: 4 scores per load
    for (int base = t * 4; base + 3 < V; base += NTHREADS * 4) {
        const float4 v4 = *reinterpret_cast<const float4*>(g_scores + base);
        #pragma unroll
        for (int q = 0; q < 4; q++) {
            const float v = (q == 0) ? v4.x : (q == 1) ? v4.y : (q == 2) ? v4.z : v4.w;
            if (v > kmin) {
                int pos = K - 1;
                while (pos > 0 && lv[pos - 1] < v) {
                    lv[pos] = lv[pos - 1];
                    li[pos] = li[pos - 1];
                    pos--;
                }
                lv[pos] = v;
                li[pos] = base + q;
                kmin = lv[K - 1];
            }
        }
    }
    // scalar tail (V not multiple of 4*NTHREADS)
    for (int r = (V & ~3) + t; r < V; r += NTHREADS) {
        const float v = g_scores[r];
        if (v > kmin) {
            int pos = K - 1;
            while (pos > 0 && lv[pos - 1] < v) {
                lv[pos] = lv[pos - 1];
                li[pos] = li[pos - 1];
                pos--;
            }
            lv[pos] = v;
            li[pos] = r;
            kmin = lv[K - 1];
        }
    }

    for (int i = 0; i < K; i++) {
        svals[t * KMAX + i] = lv[i];
        sids [t * KMAX + i] = li[i];
    }
    __syncthreads();

    // parallel binary tree merge: 256 sorted lists -> 1, log2(256)=8 levels
    for (int stride = NTHREADS / 2; stride >= 1; stride >>= 1) {
        if (t < stride) {
            float* A  = svals + t * KMAX;
            int*   Ai = sids  + t * KMAX;
            const float* B  = svals + (t + stride) * KMAX;
            const int*   Bi = sids  + (t + stride) * KMAX;
            float rv[KMAX];
            int   ri[KMAX];
            int ia = 0, ib = 0;
            for (int o = 0; o < K; o++) {
                const float va = A[ia];  const int ida = Ai[ia];
                const float vb = B[ib];  const int idb = Bi[ib];
                const bool takeA = (va > vb) || (va == vb && ida < idb);
                if (takeA) { rv[o] = va; ri[o] = ida; ia++; }
                else       { rv[o] = vb; ri[o] = idb; ib++; }
            }
            for (int o = 0; o < K; o++) { A[o] = rv[o]; Ai[o] = ri[o]; }
        }
        __syncthreads();
    }

    if (t == 0) {
        for (int i = 0; i < K && i < out_size; i++)
            out[i] = svals[i];
        if (out_size >= 2 * K) {
            for (int i = 0; i < K; i++)
                out[K + i] = (float)sids[i];
        }
        g_done = 0;   // reset for next (deterministic) replay
    }
}

// ---------------------------------------------------------------------------
extern "C" void kernel_launch(void* const* d_in, const int* in_sizes, int n_in,
                              void* d_out, int out_size)
{
    const int*   wordid = (const int*)  d_in[0];
    const float* emb    = (const float*)d_in[1];
    const int*   topk   = (const int*)  d_in[2];
    float*       out    = (float*)      d_out;

    const int V = in_sizes[1] / DIM;   // 200000

    int Hc = H_CARVE;
    if (Hc > V) Hc = V;

    fused_kernel<<<NBLOCKS, NTHREADS>>>(wordid, emb, topk, out, out_size, V, Hc);
}